// round 1
// baseline (speedup 1.0000x reference)
#include <cuda_runtime.h>

#define BATCH 128
#define SEQ   2048
#define KDIM  128
#define CAPS  32
#define DCAP  16
#define MCOLS 512      // CAPS*DCAP
#define NTILES 16
#define TILEN 128      // SEQ / NTILES

#define XS_STRIDE 132  // padded row stride for x tile in smem (floats)
#define PS_STRIDE 36   // padded row stride for probs in smem (floats)
#define SMEM_FLOATS (TILEN*XS_STRIDE + KDIM*CAPS + TILEN*PS_STRIDE)
#define SMEM_BYTES  (SMEM_FLOATS * 4)

// ---- scratch (no allocations allowed) ----
__device__ float g_Spart[BATCH][NTILES][KDIM];          // partial sums of x over n
__device__ float g_o[BATCH][CAPS][DCAP];                // current capsule outputs
__device__ float g_W2[BATCH][KDIM][CAPS];               // kernel contracted with o over d
__device__ float g_ypart[BATCH][NTILES][CAPS * KDIM];   // per-tile partial y

// ============================================================
// Kernel 1: partial column sums of x over the sequence dim.
// grid (NTILES, BATCH), block 128 (one thread per k). Coalesced.
// ============================================================
__global__ void k_reduce(const float* __restrict__ x) {
    int b = blockIdx.y, p = blockIdx.x, k = threadIdx.x;
    const float* xp = x + ((size_t)(b * SEQ + p * TILEN)) * KDIM + k;
    float s = 0.f;
#pragma unroll 8
    for (int n = 0; n < TILEN; ++n) s += xp[(size_t)n * KDIM];
    g_Spart[b][p][k] = s;
}

// ============================================================
// Kernel 2: o1 = squash((1/32) * S[b] @ kernel).  grid 128, block 512.
// thread t = c*16 + d  (one output column of kernel)
// ============================================================
__global__ void k_o_first(const float* __restrict__ w) {
    int b = blockIdx.x, t = threadIdx.x;
    __shared__ float S[KDIM];
    if (t < KDIM) {
        float s = 0.f;
#pragma unroll
        for (int p = 0; p < NTILES; ++p) s += g_Spart[b][p][t];
        S[t] = s * (1.f / 32.f);
    }
    __syncthreads();
    float acc = 0.f;
#pragma unroll 4
    for (int k = 0; k < KDIM; ++k) acc += S[k] * w[k * MCOLS + t];
    // squash over groups of 16 lanes (one capsule)
    float sq = acc * acc;
#pragma unroll
    for (int off = 8; off >= 1; off >>= 1)
        sq += __shfl_xor_sync(0xffffffffu, sq, off, 16);
    float s2 = sq + 1e-7f;
    float scale = sqrtf(s2) / (0.5f + s2);
    int c = t >> 4, d = t & 15;
    g_o[b][c][d] = scale * acc;
}

// ============================================================
// Kernel 3: W2[b,k,c] = sum_d kernel[k, c*16+d] * o[b,c,d]
// grid 128, block 256, 16 outputs per thread.
// ============================================================
__global__ void k_W2(const float* __restrict__ w) {
    int b = blockIdx.x, t = threadIdx.x;
    __shared__ float os[MCOLS];
    const float* ob = (const float*)g_o[b];
    os[t] = ob[t];
    os[t + 256] = ob[t + 256];
    __syncthreads();
#pragma unroll
    for (int i = 0; i < 16; ++i) {
        int idx = t + i * 256;
        int k = idx >> 5, c = idx & 31;
        const float* wr = w + k * MCOLS + c * DCAP;
        const float* ov = os + c * DCAP;
        float acc = 0.f;
#pragma unroll
        for (int d = 0; d < DCAP; ++d) acc += wr[d] * ov[d];
        g_W2[b][k][c] = acc;
    }
}

// ============================================================
// Kernel 4: fused routing iteration body.
//   per (batch, n-tile of 128):
//     logits = x_tile @ W2[b]      (128x32)
//     probs  = softmax over capsules (per row)
//     y_partial = probs^T @ x_tile (32x128)  -> g_ypart
// grid (NTILES, BATCH), 256 threads, 100KB dynamic smem.
// ============================================================
__global__ void k_iter(const float* __restrict__ x) {
    extern __shared__ float sm[];
    float* xs  = sm;                             // [TILEN][XS_STRIDE]
    float* w2s = sm + TILEN * XS_STRIDE;         // [KDIM][CAPS]
    float* ps  = w2s + KDIM * CAPS;              // [TILEN][PS_STRIDE]

    int b = blockIdx.y, tile = blockIdx.x, t = threadIdx.x;

    // load x tile (16384 floats), coalesced float4
    const float4* xb = (const float4*)(x + ((size_t)(b * SEQ + tile * TILEN)) * KDIM);
#pragma unroll
    for (int i = 0; i < 16; ++i) {
        int lin = t + i * 256;            // float4 index within tile
        int row = lin >> 5, c4 = lin & 31;
        float4 v = xb[row * 32 + c4];
        *(float4*)&xs[row * XS_STRIDE + c4 * 4] = v;
    }
    // load W2[b] (4096 floats)
    const float* w2g = (const float*)g_W2[b];
#pragma unroll
    for (int i = 0; i < 16; ++i) w2s[t + i * 256] = w2g[t + i * 256];
    __syncthreads();

    // ---- phase 1: logits[n][c] = sum_k xs[n][k] * w2s[k][c] ----
    {
        int tn = t & 31, tc = t >> 5;
        int c0 = tc * 4;
        float acc[4][4];
#pragma unroll
        for (int i = 0; i < 4; ++i)
#pragma unroll
            for (int j = 0; j < 4; ++j) acc[i][j] = 0.f;

        for (int k = 0; k < KDIM; k += 4) {
            float4 w0 = *(const float4*)&w2s[(k + 0) * CAPS + c0];
            float4 w1 = *(const float4*)&w2s[(k + 1) * CAPS + c0];
            float4 w2 = *(const float4*)&w2s[(k + 2) * CAPS + c0];
            float4 w3 = *(const float4*)&w2s[(k + 3) * CAPS + c0];
#pragma unroll
            for (int i = 0; i < 4; ++i) {
                int n = tn + 32 * i;
                float4 a = *(const float4*)&xs[n * XS_STRIDE + k];
                acc[i][0] += a.x * w0.x + a.y * w1.x + a.z * w2.x + a.w * w3.x;
                acc[i][1] += a.x * w0.y + a.y * w1.y + a.z * w2.y + a.w * w3.y;
                acc[i][2] += a.x * w0.z + a.y * w1.z + a.z * w2.z + a.w * w3.z;
                acc[i][3] += a.x * w0.w + a.y * w1.w + a.z * w2.w + a.w * w3.w;
            }
        }
#pragma unroll
        for (int i = 0; i < 4; ++i) {
            int n = tn + 32 * i;
#pragma unroll
            for (int j = 0; j < 4; ++j) ps[n * PS_STRIDE + c0 + j] = acc[i][j];
        }
    }
    __syncthreads();

    // ---- softmax over capsules, one thread per row ----
    if (t < TILEN) {
        float* row = &ps[t * PS_STRIDE];
        float mx = row[0];
#pragma unroll
        for (int c = 1; c < CAPS; ++c) mx = fmaxf(mx, row[c]);
        float e[CAPS];
        float sum = 0.f;
#pragma unroll
        for (int c = 0; c < CAPS; ++c) { e[c] = __expf(row[c] - mx); sum += e[c]; }
        float inv = 1.f / sum;
#pragma unroll
        for (int c = 0; c < CAPS; ++c) row[c] = e[c] * inv;
    }
    __syncthreads();

    // ---- phase 2: y[c][k] = sum_n probs[n][c] * xs[n][k] ----
    {
        int tk = t & 31, tc = t >> 5;
        int k0 = tk * 4, c0 = tc * 4;
        float acc[4][4];
#pragma unroll
        for (int j = 0; j < 4; ++j)
#pragma unroll
            for (int kk = 0; kk < 4; ++kk) acc[j][kk] = 0.f;

        for (int n = 0; n < TILEN; ++n) {
            float4 pv = *(const float4*)&ps[n * PS_STRIDE + c0];
            float4 xa = *(const float4*)&xs[n * XS_STRIDE + k0];
            acc[0][0] += pv.x * xa.x; acc[0][1] += pv.x * xa.y;
            acc[0][2] += pv.x * xa.z; acc[0][3] += pv.x * xa.w;
            acc[1][0] += pv.y * xa.x; acc[1][1] += pv.y * xa.y;
            acc[1][2] += pv.y * xa.z; acc[1][3] += pv.y * xa.w;
            acc[2][0] += pv.z * xa.x; acc[2][1] += pv.z * xa.y;
            acc[2][2] += pv.z * xa.z; acc[2][3] += pv.z * xa.w;
            acc[3][0] += pv.w * xa.x; acc[3][1] += pv.w * xa.y;
            acc[3][2] += pv.w * xa.z; acc[3][3] += pv.w * xa.w;
        }
        float* yo = &g_ypart[b][tile][0];
#pragma unroll
        for (int j = 0; j < 4; ++j) {
            float4 v = make_float4(acc[j][0], acc[j][1], acc[j][2], acc[j][3]);
            *(float4*)&yo[(c0 + j) * KDIM + k0] = v;
        }
    }
}

// ============================================================
// Kernel 5: reduce y partials, u = y @ kernel (per capsule column block),
// squash, write to g_o (out==nullptr) or to final output.
// grid 128, block 512.
// ============================================================
__global__ void k_o_final(const float* __restrict__ w, float* __restrict__ out) {
    int b = blockIdx.x, t = threadIdx.x;
    __shared__ float ys[CAPS * KDIM];
#pragma unroll
    for (int i = 0; i < 8; ++i) {
        int idx = t + i * 512;
        float s = 0.f;
#pragma unroll
        for (int p = 0; p < NTILES; ++p) s += g_ypart[b][p][idx];
        ys[idx] = s;
    }
    __syncthreads();
    int c = t >> 4, d = t & 15;
    const float* yr = &ys[c * KDIM];
    float acc = 0.f;
#pragma unroll 4
    for (int k = 0; k < KDIM; ++k) acc += yr[k] * w[k * MCOLS + t];
    float sq = acc * acc;
#pragma unroll
    for (int off = 8; off >= 1; off >>= 1)
        sq += __shfl_xor_sync(0xffffffffu, sq, off, 16);
    float s2 = sq + 1e-7f;
    float scale = sqrtf(s2) / (0.5f + s2);
    float val = scale * acc;
    if (out) out[(b * CAPS + c) * DCAP + d] = val;
    else     g_o[b][c][d] = val;
    (void)d;
}

extern "C" void kernel_launch(void* const* d_in, const int* in_sizes, int n_in,
                              void* d_out, int out_size) {
    const float* x = (const float*)d_in[0];
    const float* w = (const float*)d_in[1];
    // safety: metadata order guard (x has 33.5M elems, kernel has 65536)
    if (n_in >= 2 && in_sizes[0] == MCOLS * KDIM) {
        x = (const float*)d_in[1];
        w = (const float*)d_in[0];
    }
    (void)out_size;

    cudaFuncSetAttribute(k_iter, cudaFuncAttributeMaxDynamicSharedMemorySize, SMEM_BYTES);

    // iteration 0 (uniform coupling): o1 from column sums of x
    k_reduce<<<dim3(NTILES, BATCH), 128>>>(x);
    k_o_first<<<BATCH, 512>>>(w);

    // iterations 1 and 2
    for (int r = 0; r < 2; ++r) {
        k_W2<<<BATCH, 256>>>(w);
        k_iter<<<dim3(NTILES, BATCH), 256, SMEM_BYTES>>>(x);
        k_o_final<<<BATCH, 512>>>(w, (r == 1) ? (float*)d_out : nullptr);
    }
}

// round 2
// speedup vs baseline: 1.0020x; 1.0020x over previous
#include <cuda_runtime.h>

#define BATCH 128
#define SEQ   2048
#define KDIM  128
#define CAPS  32
#define DCAP  16
#define MCOLS 512      // CAPS*DCAP
#define NTILES 16
#define TILEN 128      // SEQ / NTILES

#define XS_STRIDE 132  // padded row stride for x tile in smem (floats)
#define PS_STRIDE 36   // padded row stride for probs in smem (floats)
#define SMEM_FLOATS (TILEN*XS_STRIDE + KDIM*CAPS + TILEN*PS_STRIDE)
#define SMEM_BYTES  (SMEM_FLOATS * 4)

// ---- scratch (no allocations allowed) ----
__device__ float g_Spart[BATCH][NTILES][KDIM];          // partial sums of x over n
__device__ float g_o[BATCH][CAPS][DCAP];                // current capsule outputs
__device__ float g_W2[BATCH][KDIM][CAPS];               // kernel contracted with o over d
__device__ float g_ypart[BATCH][NTILES][CAPS * KDIM];   // per-tile partial y

// ============================================================
// Kernel 1: partial column sums of x over the sequence dim.
// grid (NTILES, BATCH), block 128 (one thread per k). Coalesced.
// ============================================================
__global__ void k_reduce(const float* __restrict__ x) {
    int b = blockIdx.y, p = blockIdx.x, k = threadIdx.x;
    const float* xp = x + ((size_t)(b * SEQ + p * TILEN)) * KDIM + k;
    float s = 0.f;
#pragma unroll 8
    for (int n = 0; n < TILEN; ++n) s += xp[(size_t)n * KDIM];
    g_Spart[b][p][k] = s;
}

// ============================================================
// Kernel 2: o1 = squash((1/32) * S[b] @ kernel).  grid 128, block 512.
// thread t = c*16 + d  (one output column of kernel)
// ============================================================
__global__ void k_o_first(const float* __restrict__ w) {
    int b = blockIdx.x, t = threadIdx.x;
    __shared__ float S[KDIM];
    if (t < KDIM) {
        float s = 0.f;
#pragma unroll
        for (int p = 0; p < NTILES; ++p) s += g_Spart[b][p][t];
        S[t] = s * (1.f / 32.f);
    }
    __syncthreads();
    float acc = 0.f;
#pragma unroll 4
    for (int k = 0; k < KDIM; ++k) acc += S[k] * w[k * MCOLS + t];
    // squash over groups of 16 lanes (one capsule)
    float sq = acc * acc;
#pragma unroll
    for (int off = 8; off >= 1; off >>= 1)
        sq += __shfl_xor_sync(0xffffffffu, sq, off, 16);
    float s2 = sq + 1e-7f;
    float scale = sqrtf(s2) / (0.5f + s2);
    int c = t >> 4, d = t & 15;
    g_o[b][c][d] = scale * acc;
}

// ============================================================
// Kernel 3: W2[b,k,c] = sum_d kernel[k, c*16+d] * o[b,c,d]
// grid 128, block 256, 16 outputs per thread.
// ============================================================
__global__ void k_W2(const float* __restrict__ w) {
    int b = blockIdx.x, t = threadIdx.x;
    __shared__ float os[MCOLS];
    const float* ob = (const float*)g_o[b];
    os[t] = ob[t];
    os[t + 256] = ob[t + 256];
    __syncthreads();
#pragma unroll
    for (int i = 0; i < 16; ++i) {
        int idx = t + i * 256;
        int k = idx >> 5, c = idx & 31;
        const float* wr = w + k * MCOLS + c * DCAP;
        const float* ov = os + c * DCAP;
        float acc = 0.f;
#pragma unroll
        for (int d = 0; d < DCAP; ++d) acc += wr[d] * ov[d];
        g_W2[b][k][c] = acc;
    }
}

// ============================================================
// Kernel 4: fused routing iteration body.
//   per (batch, n-tile of 128):
//     logits = x_tile @ W2[b]      (128x32)
//     probs  = softmax over capsules (per row)
//     y_partial = probs^T @ x_tile (32x128)  -> g_ypart
// grid (NTILES, BATCH), 256 threads, 100KB dynamic smem.
// ============================================================
__global__ void k_iter(const float* __restrict__ x) {
    extern __shared__ float sm[];
    float* xs  = sm;                             // [TILEN][XS_STRIDE]
    float* w2s = sm + TILEN * XS_STRIDE;         // [KDIM][CAPS]
    float* ps  = w2s + KDIM * CAPS;              // [TILEN][PS_STRIDE]

    int b = blockIdx.y, tile = blockIdx.x, t = threadIdx.x;

    // load x tile (16384 floats), coalesced float4
    const float4* xb = (const float4*)(x + ((size_t)(b * SEQ + tile * TILEN)) * KDIM);
#pragma unroll
    for (int i = 0; i < 16; ++i) {
        int lin = t + i * 256;            // float4 index within tile
        int row = lin >> 5, c4 = lin & 31;
        float4 v = xb[row * 32 + c4];
        *(float4*)&xs[row * XS_STRIDE + c4 * 4] = v;
    }
    // load W2[b] (4096 floats)
    const float* w2g = (const float*)g_W2[b];
#pragma unroll
    for (int i = 0; i < 16; ++i) w2s[t + i * 256] = w2g[t + i * 256];
    __syncthreads();

    // ---- phase 1: logits[n][c] = sum_k xs[n][k] * w2s[k][c] ----
    {
        int tn = t & 31, tc = t >> 5;
        int c0 = tc * 4;
        float acc[4][4];
#pragma unroll
        for (int i = 0; i < 4; ++i)
#pragma unroll
            for (int j = 0; j < 4; ++j) acc[i][j] = 0.f;

        for (int k = 0; k < KDIM; k += 4) {
            float4 w0 = *(const float4*)&w2s[(k + 0) * CAPS + c0];
            float4 w1 = *(const float4*)&w2s[(k + 1) * CAPS + c0];
            float4 w2 = *(const float4*)&w2s[(k + 2) * CAPS + c0];
            float4 w3 = *(const float4*)&w2s[(k + 3) * CAPS + c0];
#pragma unroll
            for (int i = 0; i < 4; ++i) {
                int n = tn + 32 * i;
                float4 a = *(const float4*)&xs[n * XS_STRIDE + k];
                acc[i][0] += a.x * w0.x + a.y * w1.x + a.z * w2.x + a.w * w3.x;
                acc[i][1] += a.x * w0.y + a.y * w1.y + a.z * w2.y + a.w * w3.y;
                acc[i][2] += a.x * w0.z + a.y * w1.z + a.z * w2.z + a.w * w3.z;
                acc[i][3] += a.x * w0.w + a.y * w1.w + a.z * w2.w + a.w * w3.w;
            }
        }
#pragma unroll
        for (int i = 0; i < 4; ++i) {
            int n = tn + 32 * i;
#pragma unroll
            for (int j = 0; j < 4; ++j) ps[n * PS_STRIDE + c0 + j] = acc[i][j];
        }
    }
    __syncthreads();

    // ---- softmax over capsules, one thread per row ----
    if (t < TILEN) {
        float* row = &ps[t * PS_STRIDE];
        float mx = row[0];
#pragma unroll
        for (int c = 1; c < CAPS; ++c) mx = fmaxf(mx, row[c]);
        float e[CAPS];
        float sum = 0.f;
#pragma unroll
        for (int c = 0; c < CAPS; ++c) { e[c] = __expf(row[c] - mx); sum += e[c]; }
        float inv = 1.f / sum;
#pragma unroll
        for (int c = 0; c < CAPS; ++c) row[c] = e[c] * inv;
    }
    __syncthreads();

    // ---- phase 2: y[c][k] = sum_n probs[n][c] * xs[n][k] ----
    {
        int tk = t & 31, tc = t >> 5;
        int k0 = tk * 4, c0 = tc * 4;
        float acc[4][4];
#pragma unroll
        for (int j = 0; j < 4; ++j)
#pragma unroll
            for (int kk = 0; kk < 4; ++kk) acc[j][kk] = 0.f;

        for (int n = 0; n < TILEN; ++n) {
            float4 pv = *(const float4*)&ps[n * PS_STRIDE + c0];
            float4 xa = *(const float4*)&xs[n * XS_STRIDE + k0];
            acc[0][0] += pv.x * xa.x; acc[0][1] += pv.x * xa.y;
            acc[0][2] += pv.x * xa.z; acc[0][3] += pv.x * xa.w;
            acc[1][0] += pv.y * xa.x; acc[1][1] += pv.y * xa.y;
            acc[1][2] += pv.y * xa.z; acc[1][3] += pv.y * xa.w;
            acc[2][0] += pv.z * xa.x; acc[2][1] += pv.z * xa.y;
            acc[2][2] += pv.z * xa.z; acc[2][3] += pv.z * xa.w;
            acc[3][0] += pv.w * xa.x; acc[3][1] += pv.w * xa.y;
            acc[3][2] += pv.w * xa.z; acc[3][3] += pv.w * xa.w;
        }
        float* yo = &g_ypart[b][tile][0];
#pragma unroll
        for (int j = 0; j < 4; ++j) {
            float4 v = make_float4(acc[j][0], acc[j][1], acc[j][2], acc[j][3]);
            *(float4*)&yo[(c0 + j) * KDIM + k0] = v;
        }
    }
}

// ============================================================
// Kernel 5: reduce y partials, u = y @ kernel (per capsule column block),
// squash, write to g_o (out==nullptr) or to final output.
// grid 128, block 512.
// ============================================================
__global__ void k_o_final(const float* __restrict__ w, float* __restrict__ out) {
    int b = blockIdx.x, t = threadIdx.x;
    __shared__ float ys[CAPS * KDIM];
#pragma unroll
    for (int i = 0; i < 8; ++i) {
        int idx = t + i * 512;
        float s = 0.f;
#pragma unroll
        for (int p = 0; p < NTILES; ++p) s += g_ypart[b][p][idx];
        ys[idx] = s;
    }
    __syncthreads();
    int c = t >> 4, d = t & 15;
    const float* yr = &ys[c * KDIM];
    float acc = 0.f;
#pragma unroll 4
    for (int k = 0; k < KDIM; ++k) acc += yr[k] * w[k * MCOLS + t];
    float sq = acc * acc;
#pragma unroll
    for (int off = 8; off >= 1; off >>= 1)
        sq += __shfl_xor_sync(0xffffffffu, sq, off, 16);
    float s2 = sq + 1e-7f;
    float scale = sqrtf(s2) / (0.5f + s2);
    float val = scale * acc;
    if (out) out[(b * CAPS + c) * DCAP + d] = val;
    else     g_o[b][c][d] = val;
    (void)d;
}

extern "C" void kernel_launch(void* const* d_in, const int* in_sizes, int n_in,
                              void* d_out, int out_size) {
    const float* x = (const float*)d_in[0];
    const float* w = (const float*)d_in[1];
    // safety: metadata order guard (x has 33.5M elems, kernel has 65536)
    if (n_in >= 2 && in_sizes[0] == MCOLS * KDIM) {
        x = (const float*)d_in[1];
        w = (const float*)d_in[0];
    }
    (void)out_size;

    cudaFuncSetAttribute(k_iter, cudaFuncAttributeMaxDynamicSharedMemorySize, SMEM_BYTES);

    // iteration 0 (uniform coupling): o1 from column sums of x
    k_reduce<<<dim3(NTILES, BATCH), 128>>>(x);
    k_o_first<<<BATCH, 512>>>(w);

    // iterations 1 and 2
    for (int r = 0; r < 2; ++r) {
        k_W2<<<BATCH, 256>>>(w);
        k_iter<<<dim3(NTILES, BATCH), 256, SMEM_BYTES>>>(x);
        k_o_final<<<BATCH, 512>>>(w, (r == 1) ? (float*)d_out : nullptr);
    }
}

// round 3
// speedup vs baseline: 1.1748x; 1.1724x over previous
#include <cuda_runtime.h>

#define BATCH 128
#define SEQ   2048
#define KDIM  128
#define CAPS  32
#define DCAP  16
#define MCOLS 512      // CAPS*DCAP
#define NTILES 16
#define TILEN 128      // SEQ / NTILES

#define XS_STRIDE 132  // padded row stride for x tile in smem (floats)
#define PS_STRIDE 36   // padded row stride for probs in smem (floats)
#define SMEM_FLOATS (TILEN*XS_STRIDE + KDIM*CAPS + TILEN*PS_STRIDE)
#define SMEM_BYTES  (SMEM_FLOATS * 4)

typedef unsigned long long u64;

// ---- packed f32x2 helpers (FFMA2: 2 exact fp32 FMAs per instruction) ----
__device__ __forceinline__ u64 f2dup(float v) {
    u64 r; asm("mov.b64 %0, {%1, %1};" : "=l"(r) : "f"(v)); return r;
}
__device__ __forceinline__ u64 ffma2(u64 a, u64 b, u64 c) {
    u64 d; asm("fma.rn.f32x2 %0, %1, %2, %3;" : "=l"(d) : "l"(a), "l"(b), "l"(c));
    return d;
}
__device__ __forceinline__ float2 f2unpack(u64 v) {
    float2 f; asm("mov.b64 {%0, %1}, %2;" : "=f"(f.x), "=f"(f.y) : "l"(v)); return f;
}

// ---- scratch (no allocations allowed) ----
__device__ float g_Spart[BATCH][NTILES][KDIM];          // partial sums of x over n
__device__ float g_W2[BATCH][KDIM][CAPS];               // kernel contracted with o over d
__device__ float g_ypart[BATCH][NTILES][CAPS * KDIM];   // per-tile partial y

// ============================================================
// Kernel 1: partial column sums of x over sequence dim (float4, high MLP).
// grid (NTILES, BATCH), block 256.
// ============================================================
__global__ void k_reduce(const float* __restrict__ x) {
    int b = blockIdx.y, p = blockIdx.x, t = threadIdx.x;
    int k4 = t & 31, rr = t >> 5;
    __shared__ float4 red[8][32];
    const float4* xp = (const float4*)(x + ((size_t)(b * SEQ + p * TILEN)) * KDIM);
    float4 s = make_float4(0.f, 0.f, 0.f, 0.f);
#pragma unroll
    for (int j = 0; j < 16; ++j) {
        float4 v = xp[(rr + 8 * j) * 32 + k4];
        s.x += v.x; s.y += v.y; s.z += v.z; s.w += v.w;
    }
    red[rr][k4] = s;
    __syncthreads();
    if (t < 32) {
        float4 a = red[0][t];
#pragma unroll
        for (int r = 1; r < 8; ++r) {
            float4 v = red[r][t];
            a.x += v.x; a.y += v.y; a.z += v.z; a.w += v.w;
        }
        *(float4*)&g_Spart[b][p][t * 4] = a;
    }
}

// ---- W2[b,k,c] = sum_d kernel[k, c*16+d] * o[b,c,d]  (o in smem) ----
__device__ __forceinline__ void compute_W2(int b, int t,
                                           const float* os,
                                           const float* __restrict__ w) {
#pragma unroll
    for (int i = 0; i < 8; ++i) {
        int idx = t + i * 512;
        int k = idx >> 5, c = idx & 31;
        const float4* wr = (const float4*)(w + k * MCOLS + c * DCAP);
        const float4* ov = (const float4*)(os + c * DCAP);
        float acc = 0.f;
#pragma unroll
        for (int q = 0; q < 4; ++q) {
            float4 a = wr[q], o4 = ov[q];
            acc += a.x * o4.x + a.y * o4.y + a.z * o4.z + a.w * o4.w;
        }
        g_W2[b][k][c] = acc;
    }
}

// ============================================================
// Kernel 2: o1 = squash((1/32) * S[b] @ kernel), fused with W2.
// grid 128, block 512.  thread t = c*16 + d.
// ============================================================
__global__ void k_o_first(const float* __restrict__ w) {
    int b = blockIdx.x, t = threadIdx.x;
    __shared__ float S[KDIM];
    __shared__ float os[MCOLS];
    if (t < KDIM) {
        float s = 0.f;
#pragma unroll
        for (int p = 0; p < NTILES; ++p) s += g_Spart[b][p][t];
        S[t] = s * (1.f / 32.f);
    }
    __syncthreads();
    float acc = 0.f;
#pragma unroll 4
    for (int k = 0; k < KDIM; ++k) acc += S[k] * w[k * MCOLS + t];
    float sq = acc * acc;
#pragma unroll
    for (int off = 8; off >= 1; off >>= 1)
        sq += __shfl_xor_sync(0xffffffffu, sq, off, 16);
    float s2 = sq + 1e-7f;
    float scale = sqrtf(s2) / (0.5f + s2);
    os[t] = scale * acc;
    __syncthreads();
    compute_W2(b, t, os, w);
}

// ============================================================
// Kernel 3: fused routing iteration body (FFMA2).
//   logits = x_tile @ W2[b]; softmax over capsules; y_part = probs^T @ x_tile
// grid (NTILES, BATCH), 256 threads, 100KB dynamic smem.
// ============================================================
__global__ void k_iter(const float* __restrict__ x) {
    extern __shared__ float sm[];
    float* xs  = sm;                             // [TILEN][XS_STRIDE]
    float* w2s = sm + TILEN * XS_STRIDE;         // [KDIM][CAPS]
    float* ps  = w2s + KDIM * CAPS;              // [TILEN][PS_STRIDE]

    int b = blockIdx.y, tile = blockIdx.x, t = threadIdx.x;
    int wid = t >> 5, l = t & 31;

    // load x tile (coalesced float4)
    const float4* xb = (const float4*)(x + ((size_t)(b * SEQ + tile * TILEN)) * KDIM);
#pragma unroll
    for (int i = 0; i < 16; ++i) {
        int lin = t + i * 256;
        int row = lin >> 5, c4 = lin & 31;
        float4 v = xb[row * 32 + c4];
        *(float4*)&xs[row * XS_STRIDE + c4 * 4] = v;
    }
    const float* w2g = (const float*)g_W2[b];
#pragma unroll
    for (int i = 0; i < 16; ++i) w2s[t + i * 256] = w2g[t + i * 256];
    __syncthreads();

    // ---- phase 1: logits[n][c] = sum_k xs[n][k] * w2s[k][c], paired over c ----
    {
        int c0 = (wid >> 1) * 8;          // 8 capsules per warp-group (4 pairs)
        int n0 = (wid & 1) * 64 + l;      // 2 rows per thread, 32 apart
        int n1 = n0 + 32;
        u64 acc[2][4];
#pragma unroll
        for (int r = 0; r < 2; ++r)
#pragma unroll
            for (int p = 0; p < 4; ++p) acc[r][p] = 0ull;

        const float* x0 = &xs[n0 * XS_STRIDE];
        const float* x1 = &xs[n1 * XS_STRIDE];
#pragma unroll 2
        for (int k = 0; k < KDIM; k += 4) {
            float4 a0 = *(const float4*)&x0[k];
            float4 a1 = *(const float4*)&x1[k];
            float av0[4] = {a0.x, a0.y, a0.z, a0.w};
            float av1[4] = {a1.x, a1.y, a1.z, a1.w};
#pragma unroll
            for (int kk = 0; kk < 4; ++kk) {
                ulonglong2 wlo = *(const ulonglong2*)&w2s[(k + kk) * CAPS + c0];
                ulonglong2 whi = *(const ulonglong2*)&w2s[(k + kk) * CAPS + c0 + 4];
                u64 d0 = f2dup(av0[kk]);
                u64 d1 = f2dup(av1[kk]);
                acc[0][0] = ffma2(d0, wlo.x, acc[0][0]);
                acc[0][1] = ffma2(d0, wlo.y, acc[0][1]);
                acc[0][2] = ffma2(d0, whi.x, acc[0][2]);
                acc[0][3] = ffma2(d0, whi.y, acc[0][3]);
                acc[1][0] = ffma2(d1, wlo.x, acc[1][0]);
                acc[1][1] = ffma2(d1, wlo.y, acc[1][1]);
                acc[1][2] = ffma2(d1, whi.x, acc[1][2]);
                acc[1][3] = ffma2(d1, whi.y, acc[1][3]);
            }
        }
#pragma unroll
        for (int p = 0; p < 4; ++p) {
            float2 v0 = f2unpack(acc[0][p]);
            float2 v1 = f2unpack(acc[1][p]);
            *(float2*)&ps[n0 * PS_STRIDE + c0 + 2 * p] = v0;
            *(float2*)&ps[n1 * PS_STRIDE + c0 + 2 * p] = v1;
        }
    }
    __syncthreads();

    // ---- softmax over capsules, one thread per row ----
    if (t < TILEN) {
        float* row = &ps[t * PS_STRIDE];
        float mx = row[0];
#pragma unroll
        for (int c = 1; c < CAPS; ++c) mx = fmaxf(mx, row[c]);
        float e[CAPS];
        float sum = 0.f;
#pragma unroll
        for (int c = 0; c < CAPS; ++c) { e[c] = __expf(row[c] - mx); sum += e[c]; }
        float inv = 1.f / sum;
#pragma unroll
        for (int c = 0; c < CAPS; ++c) row[c] = e[c] * inv;
    }
    __syncthreads();

    // ---- phase 2: y[c][k] = sum_n probs[n][c] * xs[n][k], paired over c ----
    {
        int c0 = wid * 4;     // 4 capsules per warp (2 pairs)
        int k0 = l * 4;       // 4 k per thread
        u64 acc[2][4];        // [cpair][kk]
#pragma unroll
        for (int p = 0; p < 2; ++p)
#pragma unroll
            for (int kk = 0; kk < 4; ++kk) acc[p][kk] = 0ull;

#pragma unroll 4
        for (int n = 0; n < TILEN; ++n) {
            ulonglong2 pv = *(const ulonglong2*)&ps[n * PS_STRIDE + c0];
            float4 xa = *(const float4*)&xs[n * XS_STRIDE + k0];
            u64 xd0 = f2dup(xa.x), xd1 = f2dup(xa.y);
            u64 xd2 = f2dup(xa.z), xd3 = f2dup(xa.w);
            acc[0][0] = ffma2(pv.x, xd0, acc[0][0]);
            acc[0][1] = ffma2(pv.x, xd1, acc[0][1]);
            acc[0][2] = ffma2(pv.x, xd2, acc[0][2]);
            acc[0][3] = ffma2(pv.x, xd3, acc[0][3]);
            acc[1][0] = ffma2(pv.y, xd0, acc[1][0]);
            acc[1][1] = ffma2(pv.y, xd1, acc[1][1]);
            acc[1][2] = ffma2(pv.y, xd2, acc[1][2]);
            acc[1][3] = ffma2(pv.y, xd3, acc[1][3]);
        }
        float* yo = &g_ypart[b][tile][0];
#pragma unroll
        for (int p = 0; p < 2; ++p) {
            float2 e0 = f2unpack(acc[p][0]);
            float2 e1 = f2unpack(acc[p][1]);
            float2 e2 = f2unpack(acc[p][2]);
            float2 e3 = f2unpack(acc[p][3]);
            *(float4*)&yo[(c0 + 2 * p) * KDIM + k0] =
                make_float4(e0.x, e1.x, e2.x, e3.x);
            *(float4*)&yo[(c0 + 2 * p + 1) * KDIM + k0] =
                make_float4(e0.y, e1.y, e2.y, e3.y);
        }
    }
}

// ============================================================
// Kernel 4: reduce y partials, u = y @ kernel, squash; then either
// write final output (out != nullptr) or compute W2 for next iteration.
// grid 128, block 512.
// ============================================================
__global__ void k_o_final(const float* __restrict__ w, float* __restrict__ out) {
    int b = blockIdx.x, t = threadIdx.x;
    __shared__ float ys[CAPS * KDIM];
    __shared__ float os[MCOLS];
#pragma unroll
    for (int i = 0; i < 8; ++i) {
        int idx = t + i * 512;
        float s = 0.f;
#pragma unroll
        for (int p = 0; p < NTILES; ++p) s += g_ypart[b][p][idx];
        ys[idx] = s;
    }
    __syncthreads();
    int c = t >> 4;
    const float* yr = &ys[c * KDIM];
    float acc = 0.f;
#pragma unroll 4
    for (int k = 0; k < KDIM; ++k) acc += yr[k] * w[k * MCOLS + t];
    float sq = acc * acc;
#pragma unroll
    for (int off = 8; off >= 1; off >>= 1)
        sq += __shfl_xor_sync(0xffffffffu, sq, off, 16);
    float s2 = sq + 1e-7f;
    float scale = sqrtf(s2) / (0.5f + s2);
    float val = scale * acc;
    if (out) {
        out[b * MCOLS + t] = val;            // (b*32+c)*16+d == b*512+t
    } else {
        os[t] = val;
        __syncthreads();                     // block-uniform branch: safe
        compute_W2(b, t, os, w);
    }
}

extern "C" void kernel_launch(void* const* d_in, const int* in_sizes, int n_in,
                              void* d_out, int out_size) {
    const float* x = (const float*)d_in[0];
    const float* w = (const float*)d_in[1];
    if (n_in >= 2 && in_sizes[0] == MCOLS * KDIM) {   // metadata order guard
        x = (const float*)d_in[1];
        w = (const float*)d_in[0];
    }
    (void)out_size;

    cudaFuncSetAttribute(k_iter, cudaFuncAttributeMaxDynamicSharedMemorySize, SMEM_BYTES);

    // iteration 0 (uniform coupling): o1 from column sums of x; W2 fused
    k_reduce<<<dim3(NTILES, BATCH), 256>>>(x);
    k_o_first<<<BATCH, 512>>>(w);

    // iterations 1 and 2
    for (int r = 0; r < 2; ++r) {
        k_iter<<<dim3(NTILES, BATCH), 256, SMEM_BYTES>>>(x);
        k_o_final<<<BATCH, 512>>>(w, (r == 1) ? (float*)d_out : nullptr);
    }
}

// round 4
// speedup vs baseline: 1.1895x; 1.0126x over previous
#include <cuda_runtime.h>

#define BATCH 128
#define SEQ   2048
#define KDIM  128
#define CAPS  32
#define DCAP  16
#define MCOLS 512
#define NTILES 16
#define TILEN 128

#define XS_STRIDE 132
#define PS_STRIDE 36
#define SMEM_FLOATS (TILEN*XS_STRIDE + CAPS*KDIM + TILEN*PS_STRIDE)
#define SMEM_BYTES  (SMEM_FLOATS * 4)

typedef unsigned long long u64;

__device__ __forceinline__ u64 f2dup(float v) {
    u64 r; asm("mov.b64 %0, {%1, %1};" : "=l"(r) : "f"(v)); return r;
}
__device__ __forceinline__ u64 ffma2(u64 a, u64 b, u64 c) {
    u64 d; asm("fma.rn.f32x2 %0, %1, %2, %3;" : "=l"(d) : "l"(a), "l"(b), "l"(c));
    return d;
}
__device__ __forceinline__ u64 fadd2(u64 a, u64 b) {
    u64 d; asm("add.rn.f32x2 %0, %1, %2;" : "=l"(d) : "l"(a), "l"(b)); return d;
}
__device__ __forceinline__ float2 f2unpack(u64 v) {
    float2 f; asm("mov.b64 {%0, %1}, %2;" : "=f"(f.x), "=f"(f.y) : "l"(v)); return f;
}

// ---- scratch ----
__device__ float g_Spart[BATCH][NTILES][KDIM];
__device__ float g_W2[BATCH][CAPS][KDIM];               // k-major now
__device__ float g_ypart[BATCH][NTILES][CAPS * KDIM];
__device__ float g_y[BATCH][CAPS * KDIM];

// ============================================================
// Kernel 1: partial column sums of x. grid (NTILES, BATCH), 256 thr.
// ============================================================
__global__ void k_reduce(const float* __restrict__ x) {
    int b = blockIdx.y, p = blockIdx.x, t = threadIdx.x;
    int k4 = t & 31, rr = t >> 5;
    __shared__ float4 red[8][32];
    const float4* xp = (const float4*)(x + ((size_t)(b * SEQ + p * TILEN)) * KDIM);
    float4 s = make_float4(0.f, 0.f, 0.f, 0.f);
#pragma unroll
    for (int j = 0; j < 16; ++j) {
        float4 v = xp[(rr + 8 * j) * 32 + k4];
        s.x += v.x; s.y += v.y; s.z += v.z; s.w += v.w;
    }
    red[rr][k4] = s;
    __syncthreads();
    if (t < 32) {
        float4 a = red[0][t];
#pragma unroll
        for (int r = 1; r < 8; ++r) {
            float4 v = red[r][t];
            a.x += v.x; a.y += v.y; a.z += v.z; a.w += v.w;
        }
        *(float4*)&g_Spart[b][p][t * 4] = a;
    }
}

// ---- W2[b][c][k] = sum_d kernel[k, c*16+d] * o[b,c,d] ----
__device__ __forceinline__ void compute_W2(int b, int t,
                                           const float* os,
                                           const float* __restrict__ w) {
#pragma unroll
    for (int i = 0; i < 8; ++i) {
        int idx = t + i * 512;
        int c = idx >> 7, k = idx & 127;
        const float4* wr = (const float4*)(w + k * MCOLS + c * DCAP);
        const float4* ov = (const float4*)(os + c * DCAP);
        float acc = 0.f;
#pragma unroll
        for (int q = 0; q < 4; ++q) {
            float4 a = wr[q], o4 = ov[q];
            acc += a.x * o4.x + a.y * o4.y + a.z * o4.z + a.w * o4.w;
        }
        g_W2[b][c][k] = acc;
    }
}

// ============================================================
// Kernel 2: o1 = squash((1/32) * S[b] @ kernel) + fused W2. grid 128, 512 thr.
// ============================================================
__global__ void k_o_first(const float* __restrict__ w) {
    int b = blockIdx.x, t = threadIdx.x;
    __shared__ float S[KDIM];
    __shared__ float os[MCOLS];
    if (t < KDIM) {
        float s = 0.f;
#pragma unroll
        for (int p = 0; p < NTILES; ++p) s += g_Spart[b][p][t];
        S[t] = s * (1.f / 32.f);
    }
    __syncthreads();
    float acc = 0.f;
#pragma unroll 4
    for (int k = 0; k < KDIM; ++k) acc += S[k] * w[k * MCOLS + t];
    float sq = acc * acc;
#pragma unroll
    for (int off = 8; off >= 1; off >>= 1)
        sq += __shfl_xor_sync(0xffffffffu, sq, off, 16);
    float s2 = sq + 1e-7f;
    float scale = sqrtf(s2) / (0.5f + s2);
    os[t] = scale * acc;
    __syncthreads();
    compute_W2(b, t, os, w);
}

// ============================================================
// Kernel 3: fused routing iteration (FFMA2, k-paired phase1, c-paired phase2).
// grid (NTILES, BATCH), 256 threads, 100KB dynamic smem.
// ============================================================
__global__ void __launch_bounds__(256, 2) k_iter(const float* __restrict__ x) {
    extern __shared__ float sm[];
    float* xs  = sm;                             // [TILEN][XS_STRIDE]
    float* w2t = sm + TILEN * XS_STRIDE;         // [CAPS][KDIM] (k-major)
    float* ps  = w2t + CAPS * KDIM;              // [TILEN][PS_STRIDE]
    u64* buf   = (u64*)w2t;                      // reused in phase-2 epilogue [16][128]

    int b = blockIdx.y, tile = blockIdx.x, t = threadIdx.x;
    int wid = t >> 5, l = t & 31;

    // prologue: load x tile + W2
    const float4* xb = (const float4*)(x + ((size_t)(b * SEQ + tile * TILEN)) * KDIM);
#pragma unroll
    for (int i = 0; i < 16; ++i) {
        int lin = t + i * 256;
        int row = lin >> 5, c4 = lin & 31;
        float4 v = xb[row * 32 + c4];
        *(float4*)&xs[row * XS_STRIDE + c4 * 4] = v;
    }
    const float* w2g = (const float*)g_W2[b];
#pragma unroll
    for (int i = 0; i < 16; ++i) w2t[t + i * 256] = w2g[t + i * 256];
    __syncthreads();

    // ---- phase 1: logits[n][c] = sum_k xs[n][k]*w2t[c][k], k-paired FFMA2 ----
    {
        int c0 = wid * 4;                 // 4 capsules per warp
        u64 acc[4][4];                    // [n-idx][c-idx], packed (even-k, odd-k)
#pragma unroll
        for (int i = 0; i < 4; ++i)
#pragma unroll
            for (int j = 0; j < 4; ++j) acc[i][j] = 0ull;

#pragma unroll 4
        for (int k = 0; k < KDIM; k += 4) {
            ulonglong2 xa[4];
#pragma unroll
            for (int i = 0; i < 4; ++i)
                xa[i] = *(const ulonglong2*)&xs[(l + 32 * i) * XS_STRIDE + k];
            ulonglong2 wv[4];
#pragma unroll
            for (int j = 0; j < 4; ++j)
                wv[j] = *(const ulonglong2*)&w2t[(c0 + j) * KDIM + k];
#pragma unroll
            for (int i = 0; i < 4; ++i)
#pragma unroll
                for (int j = 0; j < 4; ++j) {
                    acc[i][j] = ffma2(xa[i].x, wv[j].x, acc[i][j]);
                    acc[i][j] = ffma2(xa[i].y, wv[j].y, acc[i][j]);
                }
        }
#pragma unroll
        for (int i = 0; i < 4; ++i) {
            float4 out;
            float2 e0 = f2unpack(acc[i][0]);
            float2 e1 = f2unpack(acc[i][1]);
            float2 e2 = f2unpack(acc[i][2]);
            float2 e3 = f2unpack(acc[i][3]);
            out.x = e0.x + e0.y; out.y = e1.x + e1.y;
            out.z = e2.x + e2.y; out.w = e3.x + e3.y;
            *(float4*)&ps[(l + 32 * i) * PS_STRIDE + c0] = out;
        }
    }
    __syncthreads();

    // ---- softmax over capsules, one thread per row ----
    if (t < TILEN) {
        float* row = &ps[t * PS_STRIDE];
        float mx = row[0];
#pragma unroll
        for (int c = 1; c < CAPS; ++c) mx = fmaxf(mx, row[c]);
        float e[CAPS];
        float sum = 0.f;
#pragma unroll
        for (int c = 0; c < CAPS; ++c) { e[c] = __expf(row[c] - mx); sum += e[c]; }
        float inv = 1.f / sum;
#pragma unroll
        for (int c = 0; c < CAPS; ++c) row[c] = e[c] * inv;
    }
    __syncthreads();

    // ---- phase 2: y[c][k] = sum_n probs[n][c]*xs[n][k] ----
    // warp w: c0=(w&3)*8 (4 c-pairs), n-half nh=w>>2; smem-combine halves.
    {
        int g = wid & 3, nh = wid >> 2;
        int c0 = g * 8;
        int k0 = l * 4;
        u64 acc[4][4];                    // [c-pair][kk]
#pragma unroll
        for (int p = 0; p < 4; ++p)
#pragma unroll
            for (int kk = 0; kk < 4; ++kk) acc[p][kk] = 0ull;

        int nbase = nh * 64;
#pragma unroll 4
        for (int nn = 0; nn < 64; ++nn) {
            int n = nbase + nn;
            ulonglong2 pv0 = *(const ulonglong2*)&ps[n * PS_STRIDE + c0];
            ulonglong2 pv1 = *(const ulonglong2*)&ps[n * PS_STRIDE + c0 + 4];
            float4 xa = *(const float4*)&xs[n * XS_STRIDE + k0];
            u64 xd0 = f2dup(xa.x), xd1 = f2dup(xa.y);
            u64 xd2 = f2dup(xa.z), xd3 = f2dup(xa.w);
            acc[0][0] = ffma2(pv0.x, xd0, acc[0][0]);
            acc[0][1] = ffma2(pv0.x, xd1, acc[0][1]);
            acc[0][2] = ffma2(pv0.x, xd2, acc[0][2]);
            acc[0][3] = ffma2(pv0.x, xd3, acc[0][3]);
            acc[1][0] = ffma2(pv0.y, xd0, acc[1][0]);
            acc[1][1] = ffma2(pv0.y, xd1, acc[1][1]);
            acc[1][2] = ffma2(pv0.y, xd2, acc[1][2]);
            acc[1][3] = ffma2(pv0.y, xd3, acc[1][3]);
            acc[2][0] = ffma2(pv1.x, xd0, acc[2][0]);
            acc[2][1] = ffma2(pv1.x, xd1, acc[2][1]);
            acc[2][2] = ffma2(pv1.x, xd2, acc[2][2]);
            acc[2][3] = ffma2(pv1.x, xd3, acc[2][3]);
            acc[3][0] = ffma2(pv1.y, xd0, acc[3][0]);
            acc[3][1] = ffma2(pv1.y, xd1, acc[3][1]);
            acc[3][2] = ffma2(pv1.y, xd2, acc[3][2]);
            acc[3][3] = ffma2(pv1.y, xd3, acc[3][3]);
        }
        __syncthreads();   // all reads of ps/w2t done; buf overlays w2t
        if (nh == 1) {
#pragma unroll
            for (int p = 0; p < 4; ++p)
#pragma unroll
                for (int kk = 0; kk < 4; ++kk)
                    buf[(p * 4 + kk) * 128 + g * 32 + l] = acc[p][kk];
        }
        __syncthreads();
        if (nh == 0) {
            float* yo = &g_ypart[b][tile][0];
#pragma unroll
            for (int p = 0; p < 4; ++p) {
#pragma unroll
                for (int kk = 0; kk < 4; ++kk)
                    acc[p][kk] = fadd2(acc[p][kk], buf[(p * 4 + kk) * 128 + g * 32 + l]);
                float2 e0 = f2unpack(acc[p][0]);
                float2 e1 = f2unpack(acc[p][1]);
                float2 e2 = f2unpack(acc[p][2]);
                float2 e3 = f2unpack(acc[p][3]);
                *(float4*)&yo[(c0 + 2 * p) * KDIM + k0] =
                    make_float4(e0.x, e1.x, e2.x, e3.x);
                *(float4*)&yo[(c0 + 2 * p + 1) * KDIM + k0] =
                    make_float4(e0.y, e1.y, e2.y, e3.y);
            }
        }
    }
}

// ============================================================
// Kernel 4: wide reduction of y partials. grid (8, BATCH), 512 thr.
// ============================================================
__global__ void k_yred() {
    int b = blockIdx.y, t = threadIdx.x;
    int idx = blockIdx.x * 512 + t;
    float s = 0.f;
#pragma unroll
    for (int p = 0; p < NTILES; ++p) s += g_ypart[b][p][idx];
    g_y[b][idx] = s;
}

// ============================================================
// Kernel 5: u = y @ kernel, squash; write output or fused W2.
// grid 128, 512 thr.
// ============================================================
__global__ void k_fin(const float* __restrict__ w, float* __restrict__ out) {
    int b = blockIdx.x, t = threadIdx.x;
    __shared__ float ys[CAPS * KDIM];
    __shared__ float os[MCOLS];
#pragma unroll
    for (int i = 0; i < 8; ++i) ys[t + i * 512] = g_y[b][t + i * 512];
    __syncthreads();
    int c = t >> 4;
    const float* yr = &ys[c * KDIM];
    float acc = 0.f;
#pragma unroll 8
    for (int k = 0; k < KDIM; ++k) acc += yr[k] * w[k * MCOLS + t];
    float sq = acc * acc;
#pragma unroll
    for (int off = 8; off >= 1; off >>= 1)
        sq += __shfl_xor_sync(0xffffffffu, sq, off, 16);
    float s2 = sq + 1e-7f;
    float scale = sqrtf(s2) / (0.5f + s2);
    float val = scale * acc;
    if (out) {
        out[b * MCOLS + t] = val;
    } else {
        os[t] = val;
        __syncthreads();
        compute_W2(b, t, os, w);
    }
}

extern "C" void kernel_launch(void* const* d_in, const int* in_sizes, int n_in,
                              void* d_out, int out_size) {
    const float* x = (const float*)d_in[0];
    const float* w = (const float*)d_in[1];
    if (n_in >= 2 && in_sizes[0] == MCOLS * KDIM) {
        x = (const float*)d_in[1];
        w = (const float*)d_in[0];
    }
    (void)out_size;

    cudaFuncSetAttribute(k_iter, cudaFuncAttributeMaxDynamicSharedMemorySize, SMEM_BYTES);

    k_reduce<<<dim3(NTILES, BATCH), 256>>>(x);
    k_o_first<<<BATCH, 512>>>(w);

    for (int r = 0; r < 2; ++r) {
        k_iter<<<dim3(NTILES, BATCH), 256, SMEM_BYTES>>>(x);
        k_yred<<<dim3(8, BATCH), 512>>>();
        k_fin<<<BATCH, 512>>>(w, (r == 1) ? (float*)d_out : nullptr);
    }
}